// round 1
// baseline (speedup 1.0000x reference)
#include <cuda_runtime.h>

#define NPTS 2097152
#define NSTR 500
#define PPT  4
#define TPB  256

typedef unsigned long long ull;

// ---- f32x2 packed helpers (sm_103a) ----
__device__ __forceinline__ ull pk2(float lo, float hi) {
    ull r; asm("mov.b64 %0, {%1,%2};" : "=l"(r) : "f"(lo), "f"(hi)); return r;
}
__device__ __forceinline__ void upk2(ull v, float& lo, float& hi) {
    asm("mov.b64 {%0,%1}, %2;" : "=f"(lo), "=f"(hi) : "l"(v));
}
__device__ __forceinline__ ull add2(ull a, ull b) {
    ull r; asm("add.rn.f32x2 %0, %1, %2;" : "=l"(r) : "l"(a), "l"(b)); return r;
}
__device__ __forceinline__ ull mul2(ull a, ull b) {
    ull r; asm("mul.rn.f32x2 %0, %1, %2;" : "=l"(r) : "l"(a), "l"(b)); return r;
}
__device__ __forceinline__ ull fma2_(ull a, ull b, ull c) {
    ull r; asm("fma.rn.f32x2 %0, %1, %2, %3;" : "=l"(r) : "l"(a), "l"(b), "l"(c)); return r;
}
__device__ __forceinline__ float sqap(float x) {
    float y; asm("sqrt.approx.f32 %0, %1;" : "=f"(y) : "f"(x)); return y;
}
// t = saturate(dist * (-5.0) + b)   -- FFMA-imm form, rt=1
__device__ __forceinline__ float fmasat_m5(float dist, float b) {
    float d; asm("fma.rn.sat.f32 %0, %1, 0fC0A00000, %2;" : "=f"(d) : "f"(dist), "f"(b));
    return d;
}

__global__ __launch_bounds__(TPB)
void stroke_field_kernel(const float* __restrict__ coords,
                         const float4* __restrict__ shape,   // [S,4] (cx,cy,cz,r)
                         const float*  __restrict__ color,   // [S,3]
                         const float*  __restrict__ alpha,   // [S,1]
                         float* __restrict__ out)
{
    // Preprocessed stroke data:
    // sh0[s] = {-cx, -cy, cr, cg}
    // sh1[s] = {cb, dens, -cz, b}   with dens = max(alpha,0)*50, b = 5r + 0.5
    __shared__ float4 sh0[NSTR];
    __shared__ float4 sh1[NSTR];
    for (int s = threadIdx.x; s < NSTR; s += TPB) {
        float4 sp = shape[s];
        float cr = color[3 * s + 0];
        float cg = color[3 * s + 1];
        float cb = color[3 * s + 2];
        float dens = fmaxf(alpha[s], 0.0f) * 50.0f;
        sh0[s] = make_float4(-sp.x, -sp.y, cr, cg);
        sh1[s] = make_float4(cb, dens, -sp.z, fmaf(sp.w, 5.0f, 0.5f));
    }
    __syncthreads();

    const int base = blockIdx.x * (TPB * PPT) + threadIdx.x;

    ull   pxy[PPT];           // warped (x,y)
    float pz [PPT];           // warped z
    ull   hrg[PPT];           // state (r, g)
    ull   hbd[PPT];           // state (b, density)
    float w  [PPT];           // color weight

#pragma unroll
    for (int k = 0; k < PPT; k++) {
        int i = base + k * TPB;
        float x = coords[3 * i + 0];
        float y = coords[3 * i + 1];
        float z = coords[3 * i + 2];
        // mip-NeRF-360 contraction, then /2
        float n2 = fmaf(x, x, fmaf(y, y, z * z));
        float n  = sqrtf(n2);
        float scale = 0.5f;
        if (n > 1.0f) scale = (2.0f - 1.0f / n) * (0.5f / n);
        pxy[k] = pk2(x * scale, y * scale);
        pz [k] = z * scale;
        hrg[k] = 0ULL;
        hbd[k] = 0ULL;
        w  [k] = 1.0f;
    }

#pragma unroll 1
    for (int s = 0; s < NSTR; s++) {
        float4 s0 = sh0[s];
        float4 s1 = sh1[s];
        ull ncxy = pk2(s0.x, s0.y);
        ull crg  = pk2(s0.z, s0.w);
        ull cbd  = pk2(s1.x, s1.y);
        float ncz = s1.z;
        float bb  = s1.w;
#pragma unroll
        for (int k = 0; k < PPT; k++) {
            ull dxy = add2(pxy[k], ncxy);            // p - c  (xy)
            float dz = pz[k] + ncz;                  // p - c  (z)
            ull sq  = mul2(dxy, dxy);
            float lo, hi; upk2(sq, lo, hi);
            float d2 = fmaf(dz, dz, hi) + lo;
            float dist = sqap(d2);
            float t  = fmasat_m5(dist, bb);          // sat(b - 5*dist)
            float nt = -t;
            ull t2  = pk2(t, t);
            ull nt2 = pk2(nt, nt);
            // h = (1-t)*h + t*c  ==  fma(t, c, fma(-t, h, h))
            hrg[k] = fma2_(t2, crg, fma2_(nt2, hrg[k], hrg[k]));
            hbd[k] = fma2_(t2, cbd, fma2_(nt2, hbd[k], hbd[k]));
            w[k]   = fmaf(nt, w[k], w[k]);           // (1-t)*w
        }
    }

#pragma unroll
    for (int k = 0; k < PPT; k++) {
        int i = base + k * TPB;
        float hr, hg, hb, hd;
        upk2(hrg[k], hr, hg);
        upk2(hbd[k], hb, hd);
        // density
        out[i] = hd;
        // rgb = clip(h_color / (1 + 1e-6 - w), 0, 1)
        float inv = 1.0f / (1.0f + 1e-6f - w[k]);
        out[NPTS + 3 * i + 0] = __saturatef(hr * inv);
        out[NPTS + 3 * i + 1] = __saturatef(hg * inv);
        out[NPTS + 3 * i + 2] = __saturatef(hb * inv);
        // warped coords
        float px, py; upk2(pxy[k], px, py);
        out[4 * NPTS + 3 * i + 0] = px;
        out[4 * NPTS + 3 * i + 1] = py;
        out[4 * NPTS + 3 * i + 2] = pz[k];
    }
}

extern "C" void kernel_launch(void* const* d_in, const int* in_sizes, int n_in,
                              void* d_out, int out_size)
{
    const float*  coords = (const float*)d_in[0];
    const float4* shape  = (const float4*)d_in[1];
    const float*  color  = (const float*)d_in[2];
    const float*  alpha  = (const float*)d_in[3];
    float* out = (float*)d_out;

    const int grid = NPTS / (TPB * PPT);   // 2048
    stroke_field_kernel<<<grid, TPB>>>(coords, shape, color, alpha, out);
}

// round 2
// speedup vs baseline: 2.8285x; 2.8285x over previous
#include <cuda_runtime.h>

#define NPTS   2097152
#define NSTR   500
#define NCELLS 4096          // 16^3 grid over [-1,1]^3
#define TPB    256
#define PPT    4
#define PTS_PER_BLOCK (TPB * PPT)   // 1024

typedef unsigned long long ull;
typedef unsigned int uint;

// ---- scratch (static device allocation is allowed) ----
__device__ float4 g_tmpPts[NPTS];      // warped coords (w unused)
__device__ float4 g_sortedPts[NPTS];   // warped coords, w = orig index (bitcast)
__device__ int    g_cellOf[NPTS];
__device__ uint   g_cursor[NCELLS];    // counts -> exclusive offsets -> scatter cursors
__device__ float4 g_s0[NSTR];          // {-cx, -cy, cr, cg}
__device__ float4 g_s1[NSTR];          // {cb, dens, -cz, b=5r+0.5}

// ---- f32x2 packed helpers (sm_103a) ----
__device__ __forceinline__ ull pk2(float lo, float hi) {
    ull r; asm("mov.b64 %0, {%1,%2};" : "=l"(r) : "f"(lo), "f"(hi)); return r;
}
__device__ __forceinline__ void upk2(ull v, float& lo, float& hi) {
    asm("mov.b64 {%0,%1}, %2;" : "=f"(lo), "=f"(hi) : "l"(v));
}
__device__ __forceinline__ ull add2(ull a, ull b) {
    ull r; asm("add.rn.f32x2 %0, %1, %2;" : "=l"(r) : "l"(a), "l"(b)); return r;
}
__device__ __forceinline__ ull mul2(ull a, ull b) {
    ull r; asm("mul.rn.f32x2 %0, %1, %2;" : "=l"(r) : "l"(a), "l"(b)); return r;
}
__device__ __forceinline__ ull fma2_(ull a, ull b, ull c) {
    ull r; asm("fma.rn.f32x2 %0, %1, %2, %3;" : "=l"(r) : "l"(a), "l"(b), "l"(c)); return r;
}
__device__ __forceinline__ float sqap(float x) {
    float y; asm("sqrt.approx.f32 %0, %1;" : "=f"(y) : "f"(x)); return y;
}
// t = saturate(dist * (-5.0) + b)   -- FFMA-imm form, rt=1
__device__ __forceinline__ float fmasat_m5(float dist, float b) {
    float d; asm("fma.rn.sat.f32 %0, %1, 0fC0A00000, %2;" : "=f"(d) : "f"(dist), "f"(b));
    return d;
}

// 4-bit Morton spread: b3b2b1b0 -> bits 9,6,3,0
__device__ __forceinline__ uint mort4(uint v) {
    v &= 15u;
    v = (v | (v << 4)) & 0xC3u;
    v = (v | (v << 2)) & 0x249u;
    return v;
}

// ---- Pass A: zero cursors + preprocess strokes ----
__global__ void prep_kernel(const float4* __restrict__ shape,
                            const float*  __restrict__ color,
                            const float*  __restrict__ alpha)
{
    int i = blockIdx.x * blockDim.x + threadIdx.x;   // 0..4095
    if (i < NCELLS) g_cursor[i] = 0u;
    if (i < NSTR) {
        float4 sp = shape[i];
        float cr = color[3 * i + 0];
        float cg = color[3 * i + 1];
        float cb = color[3 * i + 2];
        float dens = fmaxf(alpha[i], 0.0f) * 50.0f;
        g_s0[i] = make_float4(-sp.x, -sp.y, cr, cg);
        g_s1[i] = make_float4(cb, dens, -sp.z, fmaf(sp.w, 5.0f, 0.5f));
    }
}

// ---- Pass B: warp coords, write coords output, bin-count ----
__global__ __launch_bounds__(TPB)
void bin_kernel(const float* __restrict__ coords, float* __restrict__ out)
{
    int i = blockIdx.x * TPB + threadIdx.x;
    float x = coords[3 * i + 0];
    float y = coords[3 * i + 1];
    float z = coords[3 * i + 2];
    float n2 = fmaf(x, x, fmaf(y, y, z * z));
    float n  = sqrtf(n2);
    float scale = 0.5f;
    if (n > 1.0f) scale = (2.0f - 1.0f / n) * (0.5f / n);
    float px = x * scale, py = y * scale, pz = z * scale;

    out[4 * NPTS + 3 * i + 0] = px;
    out[4 * NPTS + 3 * i + 1] = py;
    out[4 * NPTS + 3 * i + 2] = pz;
    g_tmpPts[i] = make_float4(px, py, pz, 0.0f);

    int ix = min(15, max(0, (int)((px + 1.0f) * 8.0f)));
    int iy = min(15, max(0, (int)((py + 1.0f) * 8.0f)));
    int iz = min(15, max(0, (int)((pz + 1.0f) * 8.0f)));
    int cell = (int)(mort4((uint)ix) | (mort4((uint)iy) << 1) | (mort4((uint)iz) << 2));
    g_cellOf[i] = cell;
    atomicAdd(&g_cursor[cell], 1u);
}

// ---- Pass C: single-block exclusive scan of 4096 counts (in place) ----
__global__ __launch_bounds__(1024)
void scan_kernel()
{
    __shared__ uint warpsum[32];
    int t = threadIdx.x;
    int lane = t & 31, wid = t >> 5;

    uint v[4];
    uint base_i = (uint)t * 4u;
#pragma unroll
    for (int j = 0; j < 4; j++) v[j] = g_cursor[base_i + j];
    uint local = v[0] + v[1] + v[2] + v[3];

    uint x = local;
#pragma unroll
    for (int d = 1; d < 32; d <<= 1) {
        uint y = __shfl_up_sync(0xffffffffu, x, d);
        if (lane >= d) x += y;
    }
    if (lane == 31) warpsum[wid] = x;
    __syncthreads();
    if (wid == 0) {
        uint w = warpsum[lane];
#pragma unroll
        for (int d = 1; d < 32; d <<= 1) {
            uint y = __shfl_up_sync(0xffffffffu, w, d);
            if (lane >= d) w += y;
        }
        warpsum[lane] = w;
    }
    __syncthreads();
    uint base = (wid ? warpsum[wid - 1] : 0u) + (x - local);
#pragma unroll
    for (int j = 0; j < 4; j++) {
        g_cursor[base_i + j] = base;
        base += v[j];
    }
}

// ---- Pass D: scatter points into cell-sorted order ----
__global__ __launch_bounds__(TPB)
void scatter_kernel()
{
    int i = blockIdx.x * TPB + threadIdx.x;
    int cell = g_cellOf[i];
    uint pos = atomicAdd(&g_cursor[cell], 1u);
    float4 v = g_tmpPts[i];
    v.w = __int_as_float(i);
    g_sortedPts[pos] = v;
}

// ---- Pass E: main blend over culled strokes ----
__global__ __launch_bounds__(TPB)
void main_kernel(float* __restrict__ out)
{
    __shared__ float4 cs0[NSTR];
    __shared__ float4 cs1[NSTR];
    __shared__ uint  wcnt[8];
    __shared__ float red[8][6];

    const int tid = threadIdx.x;
    const int lane = tid & 31, wid = tid >> 5;
    const int base = blockIdx.x * PTS_PER_BLOCK + tid;

    ull   pxy[PPT];
    float pz [PPT];
    int   orig[PPT];
    ull   hrg[PPT];
    ull   hbd[PPT];
    float w  [PPT];

    float mnx =  1e30f, mny =  1e30f, mnz =  1e30f;
    float mxx = -1e30f, mxy = -1e30f, mxz = -1e30f;

#pragma unroll
    for (int k = 0; k < PPT; k++) {
        float4 p = g_sortedPts[base + k * TPB];
        pxy[k] = pk2(p.x, p.y);
        pz [k] = p.z;
        orig[k] = __float_as_int(p.w);
        hrg[k] = 0ULL; hbd[k] = 0ULL; w[k] = 1.0f;
        mnx = fminf(mnx, p.x); mxx = fmaxf(mxx, p.x);
        mny = fminf(mny, p.y); mxy = fmaxf(mxy, p.y);
        mnz = fminf(mnz, p.z); mxz = fmaxf(mxz, p.z);
    }

    // block bbox: warp shfl reduce, then smem across 8 warps
#pragma unroll
    for (int d = 16; d; d >>= 1) {
        mnx = fminf(mnx, __shfl_xor_sync(0xffffffffu, mnx, d));
        mny = fminf(mny, __shfl_xor_sync(0xffffffffu, mny, d));
        mnz = fminf(mnz, __shfl_xor_sync(0xffffffffu, mnz, d));
        mxx = fmaxf(mxx, __shfl_xor_sync(0xffffffffu, mxx, d));
        mxy = fmaxf(mxy, __shfl_xor_sync(0xffffffffu, mxy, d));
        mxz = fmaxf(mxz, __shfl_xor_sync(0xffffffffu, mxz, d));
    }
    if (lane == 0) {
        red[wid][0] = mnx; red[wid][1] = mny; red[wid][2] = mnz;
        red[wid][3] = mxx; red[wid][4] = mxy; red[wid][5] = mxz;
    }
    __syncthreads();
#pragma unroll
    for (int ww = 0; ww < 8; ww++) {
        mnx = fminf(mnx, red[ww][0]); mny = fminf(mny, red[ww][1]); mnz = fminf(mnz, red[ww][2]);
        mxx = fmaxf(mxx, red[ww][3]); mxy = fmaxf(mxy, red[ww][4]); mxz = fmaxf(mxz, red[ww][5]);
    }
    __syncthreads();   // red reused conceptually; wcnt written next

    // ordered stream compaction of strokes intersecting the bbox
    int nlist = 0;
#pragma unroll 1
    for (int r = 0; r < 2; r++) {
        int s = r * TPB + tid;
        bool keep = false;
        float4 a0, a1;
        if (s < NSTR) {
            a0 = g_s0[s]; a1 = g_s1[s];
            float cx = -a0.x, cy = -a0.y, cz = -a1.z;
            float qx = fminf(fmaxf(cx, mnx), mxx);
            float qy = fminf(fmaxf(cy, mny), mxy);
            float qz = fminf(fmaxf(cz, mnz), mxz);
            float dx = cx - qx, dy = cy - qy, dz = cz - qz;
            float d2 = fmaf(dx, dx, fmaf(dy, dy, dz * dz));
            keep = 25.0f * d2 < a1.w * a1.w;   // dist(bbox, center) < r + 0.1
        }
        uint m = __ballot_sync(0xffffffffu, keep);
        if (lane == 0) wcnt[wid] = (uint)__popc(m);
        __syncthreads();
        int off = nlist, tot = nlist;
#pragma unroll
        for (int ww = 0; ww < 8; ww++) {
            if (ww < wid) off += (int)wcnt[ww];
            tot += (int)wcnt[ww];
        }
        if (keep) {
            int pos = off + __popc(m & ((1u << lane) - 1u));
            cs0[pos] = a0;
            cs1[pos] = a1;
        }
        nlist = tot;
        __syncthreads();
    }

    // sequential blend over surviving strokes (order preserved)
#pragma unroll 1
    for (int s = 0; s < nlist; s++) {
        float4 s0 = cs0[s];
        float4 s1 = cs1[s];
        ull ncxy = pk2(s0.x, s0.y);
        ull crg  = pk2(s0.z, s0.w);
        ull cbd  = pk2(s1.x, s1.y);
        float ncz = s1.z;
        float bb  = s1.w;
#pragma unroll
        for (int k = 0; k < PPT; k++) {
            ull dxy = add2(pxy[k], ncxy);
            float dz = pz[k] + ncz;
            ull sq  = mul2(dxy, dxy);
            float lo, hi; upk2(sq, lo, hi);
            float d2 = fmaf(dz, dz, hi) + lo;
            float dist = sqap(d2);
            float t  = fmasat_m5(dist, bb);
            float nt = -t;
            ull t2  = pk2(t, t);
            ull nt2 = pk2(nt, nt);
            hrg[k] = fma2_(t2, crg, fma2_(nt2, hrg[k], hrg[k]));
            hbd[k] = fma2_(t2, cbd, fma2_(nt2, hbd[k], hbd[k]));
            w[k]   = fmaf(nt, w[k], w[k]);
        }
    }

#pragma unroll
    for (int k = 0; k < PPT; k++) {
        int i = orig[k];
        float hr, hg, hb, hd;
        upk2(hrg[k], hr, hg);
        upk2(hbd[k], hb, hd);
        out[i] = hd;
        float inv = 1.0f / (1.0f + 1e-6f - w[k]);
        out[NPTS + 3 * i + 0] = __saturatef(hr * inv);
        out[NPTS + 3 * i + 1] = __saturatef(hg * inv);
        out[NPTS + 3 * i + 2] = __saturatef(hb * inv);
    }
}

extern "C" void kernel_launch(void* const* d_in, const int* in_sizes, int n_in,
                              void* d_out, int out_size)
{
    const float*  coords = (const float*)d_in[0];
    const float4* shape  = (const float4*)d_in[1];
    const float*  color  = (const float*)d_in[2];
    const float*  alpha  = (const float*)d_in[3];
    float* out = (float*)d_out;

    prep_kernel<<<(NCELLS + TPB - 1) / TPB, TPB>>>(shape, color, alpha);
    bin_kernel<<<NPTS / TPB, TPB>>>(coords, out);
    scan_kernel<<<1, 1024>>>();
    scatter_kernel<<<NPTS / TPB, TPB>>>();
    main_kernel<<<NPTS / PTS_PER_BLOCK, TPB>>>(out);
}